// round 10
// baseline (speedup 1.0000x reference)
#include <cuda_runtime.h>
#include <cstdint>

// Problem constants
#define NB   32
#define NS   128
#define NW   4096      // NB*NS independent words
#define CC   32        // chars per word (time steps)
#define HH   256       // hidden
#define G3   768       // 3*H
#define EE   128       // embed dim
#define NV   262       // vocab
#define WPB  16        // words per block
#define HROW 20        // padded smem row for h (16 words + pad, 16B aligned)
#define NTILES (NW / WPB)           // 256

// weight pipeline
#define CHUNK_K      8                       // k-values per chunk
#define NCHUNK       (HH / CHUNK_K)          // 32 chunks per step
#define CHUNK_FLOATS (CHUNK_K * G3)          // 6144
#define CHUNK_BYTES  (CHUNK_FLOATS * 4)      // 24576
#define NBUF         3                       // ring depth (load 2 chunks ahead)

// dynamic smem layout (floats)
#define H_FLOATS   (HH * HROW)               // 5120 floats = 20480 B
#define SMEM_FLOATS (H_FLOATS + NBUF * CHUNK_FLOATS)
#define SMEM_BYTES  (SMEM_FLOATS * 4)        // 94208 B

typedef unsigned long long u64;

// Precomputed x-projection table: P[d][v][j] = embed[v].W_ih[d][j] + b_ih[d][j]
// (+ b_hh[j] folded in for the r and z gates, j < 512)
__device__ float g_P[2][NV][G3];
// k-major transposed recurrent weights: g_Wt[d][k][j] = W_hh[d][j][k]
__device__ float g_Wt[2][HH][G3];
// k-major transposed input weights (for coalesced prep_p)
__device__ float g_WtI[2][EE][G3];
// length-sort structures
__device__ int g_len[NW];          // per-word char length
__device__ int g_perm[NW];         // word ids sorted by length DESCENDING
__device__ int g_bucket_pos[33];   // scatter cursors

// ---------------------------------------------------------------------------
// Packed fp32x2 helpers (Blackwell 2x-rate fp32; ptxas never auto-emits)
// ---------------------------------------------------------------------------
__device__ __forceinline__ void fma2(u64& d, u64 a, u64 b) {
    asm("fma.rn.f32x2 %0, %1, %2, %3;" : "=l"(d) : "l"(a), "l"(b), "l"(d));
}
__device__ __forceinline__ u64 dup2(float x) {
    u64 r;
    asm("mov.b64 %0, {%1, %1};" : "=l"(r) : "f"(x));
    return r;
}
__device__ __forceinline__ uint32_t smem_u32(const void* p) {
    uint32_t a;
    asm("{ .reg .u64 t; cvta.to.shared.u64 t, %1; cvt.u32.u64 %0, t; }"
        : "=r"(a) : "l"(p));
    return a;
}
__device__ __forceinline__ void cp16(uint32_t dst, const void* src) {
    asm volatile("cp.async.cg.shared.global [%0], [%1], 16;"
                 :: "r"(dst), "l"(src) : "memory");
}
#define CP_COMMIT()  asm volatile("cp.async.commit_group;" ::: "memory")
#define CP_WAIT1()   asm volatile("cp.async.wait_group 1;" ::: "memory")
#define CP_WAITALL() asm volatile("cp.async.wait_all;"     ::: "memory")

// ---------------------------------------------------------------------------
// Prepack 0: transpose W_hh (768x256) and W_ih (768x128) to k-major.
// ---------------------------------------------------------------------------
__global__ void prep_tr_kernel(const float* __restrict__ Whh_fw,
                               const float* __restrict__ Whh_bw,
                               const float* __restrict__ Wih_fw,
                               const float* __restrict__ Wih_bw)
{
    int j = blockIdx.x;
    int d = blockIdx.y;
    int k = threadIdx.x;
    const float* Wh = d ? Whh_bw : Whh_fw;
    const float* Wi = d ? Wih_bw : Wih_fw;
    g_Wt[d][k][j] = Wh[(size_t)j * HH + k];
    if (k < EE) g_WtI[d][k][j] = Wi[(size_t)j * EE + k];
}

// ---------------------------------------------------------------------------
// Prepack 1: input-projection table, coalesced via g_WtI.  grid (NV, 2).
// ---------------------------------------------------------------------------
__global__ void prep_p_kernel(const float* __restrict__ embed,
                              const float* __restrict__ bih_fw,
                              const float* __restrict__ bhh_fw,
                              const float* __restrict__ bih_bw,
                              const float* __restrict__ bhh_bw)
{
    int v = blockIdx.x;
    int d = blockIdx.y;
    int tid = threadIdx.x;
    const float* bi = d ? bih_bw : bih_fw;
    const float* bh = d ? bhh_bw : bhh_fw;
    const float* ev = embed + (size_t)v * EE;
    float a0 = 0.f, a1 = 0.f, a2 = 0.f;
#pragma unroll 4
    for (int k = 0; k < EE; k++) {
        float e = __ldg(ev + k);                        // warp-broadcast
        const float* w = &g_WtI[d][k][0];
        a0 = fmaf(e, __ldg(w + tid),       a0);
        a1 = fmaf(e, __ldg(w + tid + 256), a1);
        a2 = fmaf(e, __ldg(w + tid + 512), a2);
    }
    g_P[d][v][tid]       = a0 + bi[tid]       + bh[tid];
    g_P[d][v][tid + 256] = a1 + bi[tid + 256] + bh[tid + 256];
    g_P[d][v][tid + 512] = a2 + bi[tid + 512];          // n-gate: b_hh NOT folded
}

// ---------------------------------------------------------------------------
// Prepack 2: counting sort of words by length, DESCENDING (contiguous-prefix
// mask -> len = row sum).  Output is permutation-invariant wrt scatter order.
// ---------------------------------------------------------------------------
__global__ void prep_sort_kernel(const int* __restrict__ chars_mask)
{
    __shared__ int hist[33];
    __shared__ int base[33];
    const int tid = threadIdx.x;
    if (tid < 33) hist[tid] = 0;
    __syncthreads();

    int mylen[NW / 1024];
#pragma unroll
    for (int q = 0; q < NW / 1024; q++) {
        const int n = tid + q * 1024;
        const int* row = chars_mask + n * CC;
        int len = 0;
#pragma unroll
        for (int c = 0; c < CC; c++) len += row[c];
        mylen[q] = len;
        g_len[n] = len;
        atomicAdd(&hist[32 - len], 1);
    }
    __syncthreads();

    if (tid == 0) {
        int acc = 0;
        for (int b = 0; b < 33; b++) { base[b] = acc; acc += hist[b]; }
    }
    __syncthreads();
    if (tid < 33) g_bucket_pos[tid] = base[tid];
    __syncthreads();

#pragma unroll
    for (int q = 0; q < NW / 1024; q++) {
        const int n = tid + q * 1024;
        const int pos = atomicAdd(&g_bucket_pos[32 - mylen[q]], 1);
        g_perm[pos] = n;
    }
}

// ---------------------------------------------------------------------------
// Activations
// ---------------------------------------------------------------------------
__device__ __forceinline__ float sigmoid_f(float x) {
    return __fdividef(1.f, 1.f + __expf(-x));
}
__device__ __forceinline__ float tanh_f(float x) {
    x = fmaxf(-15.f, fminf(15.f, x));
    float e = __expf(-2.f * x);
    return __fdividef(1.f - e, 1.f + e);
}

// ---------------------------------------------------------------------------
// Main recurrent kernel: packed fp32x2 + length-sorted tiles + cp.async
// weight pipeline.  Weights stream gmem -> smem via LDGSTS in 24KB chunks
// (8 k-values), 3-buffer ring, issued 2 chunks (~770 pipe-cyc) ahead of
// consumption -> no L2-latency stalls in the FFMA2 loop.  Consumption is
// conflict-free lane-consecutive LDS.32.  One wait_group + one barrier per
// chunk.  Tile = 16 length-sorted words runs only maxlen steps.
// ---------------------------------------------------------------------------
extern __shared__ float smem_dyn_f[];

__global__ void __launch_bounds__(256, 2) gru_kernel(
    const int*   __restrict__ chars,       // [NW, CC]
    const int*   __restrict__ chars_mask,  // [NW, CC]
    const int*   __restrict__ data_mask,   // [NW]
    const float* __restrict__ bhh_fw,      // [G3]
    const float* __restrict__ bhh_bw,
    float*       __restrict__ out)         // [NW, 512]
{
    float* hsm = smem_dyn_f;                       // h[k][word], 20KB
    float* wsm = smem_dyn_f + H_FLOATS;            // weight ring, 3 x 24KB
    const uint32_t wbase = smem_u32(wsm);
    __shared__ int wid_s[WPB];

    const int tid  = threadIdx.x;
    const int d    = blockIdx.y;
    const int tile = blockIdx.x;

    const float* __restrict__ Wt = &g_Wt[d][0][0];      // [256][768]
    const float  bn = (d ? bhh_bw : bhh_fw)[tid + 512]; // n-gate bias

    if (tid < WPB) wid_s[tid] = g_perm[tile * WPB + tid];
    const int maxlen = g_len[g_perm[tile * WPB]];       // first = longest
    const int total_chunks = maxlen * NCHUNK;

    // init h = 0
#pragma unroll
    for (int q = 0; q < H_FLOATS / 256; q++)            // 20 stores/thread
        hsm[tid + q * 256] = 0.f;

    // prime chunks 0 and 1 of the weight ring
#pragma unroll
    for (int c = 0; c < 2; c++) {
        const float4* src = reinterpret_cast<const float4*>(Wt + (size_t)c * CHUNK_FLOATS);
        const uint32_t dst = wbase + c * CHUNK_BYTES;
#pragma unroll
        for (int q = 0; q < CHUNK_FLOATS / 4 / 256; q++)   // 6 LDGSTS.128
            cp16(dst + (q * 256 + tid) * 16, src + q * 256 + tid);
        CP_COMMIT();
    }
    __syncthreads();

    int g = 0;                                           // global chunk counter
    for (int step = 0; step < maxlen; step++) {
        const int t = d ? (maxlen - 1 - step) : step;

        // accumulators: 8 word-pairs x 3 gates, packed fp32x2
        u64 accr[WPB / 2], accz[WPB / 2], accn[WPB / 2];
#pragma unroll
        for (int p = 0; p < WPB / 2; p++) { accr[p] = 0ull; accz[p] = 0ull; accn[p] = 0ull; }

        for (int s = 0; s < NCHUNK; s++, g++) {
            CP_WAIT1();                                  // chunk g has landed
            __syncthreads();                             // publish g; g-1 fully consumed

            // issue chunk g+2 into the buffer that held chunk g-1
            const int gn = g + 2;
            if (gn < total_chunks) {
                const int src_c = gn & (NCHUNK - 1);     // weights repeat per step
                const float4* src =
                    reinterpret_cast<const float4*>(Wt + (size_t)src_c * CHUNK_FLOATS);
                const uint32_t dst = wbase + (gn % NBUF) * CHUNK_BYTES;
#pragma unroll
                for (int q = 0; q < CHUNK_FLOATS / 4 / 256; q++)
                    cp16(dst + (q * 256 + tid) * 16, src + q * 256 + tid);
            }
            CP_COMMIT();                                 // (empty group ok at tail)

            // ---- compute 8 k from smem weights -----------------------------
            const float* __restrict__ wb = wsm + (g % NBUF) * CHUNK_FLOATS;
#pragma unroll
            for (int i = 0; i < CHUNK_K; i++) {
                const int k = s * CHUNK_K + i;
                const u64 wr2 = dup2(wb[i * G3 + tid]);
                const u64 wz2 = dup2(wb[i * G3 + tid + 256]);
                const u64 wn2 = dup2(wb[i * G3 + tid + 512]);
                const ulonglong2* __restrict__ hk =
                    reinterpret_cast<const ulonglong2*>(&hsm[k * HROW]);
#pragma unroll
                for (int q = 0; q < WPB / 4; q++) {      // 4 LDS.128 broadcast
                    ulonglong2 a = hk[q];                // words 4q..4q+3
                    fma2(accr[2 * q],     a.x, wr2);
                    fma2(accz[2 * q],     a.x, wz2);
                    fma2(accn[2 * q],     a.x, wn2);
                    fma2(accr[2 * q + 1], a.y, wr2);
                    fma2(accz[2 * q + 1], a.y, wz2);
                    fma2(accn[2 * q + 1], a.y, wn2);
                }
            }
        }

        // ---- gates (thread-local), update h --------------------------------
        __syncthreads();                                 // all h reads done
        const float* ar = reinterpret_cast<const float*>(accr);
        const float* az = reinterpret_cast<const float*>(accz);
        const float* an = reinterpret_cast<const float*>(accn);
#pragma unroll
        for (int w = 0; w < WPB; w++) {
            const int n  = wid_s[w];
            const int ch = chars[n * CC + t];
            const int mk = chars_mask[n * CC + t];
            const float* __restrict__ Prow = &g_P[d][ch][0];
            float xr = Prow[tid];                        // b_ih + b_hh folded
            float xz = Prow[tid + 256];
            float xn = Prow[tid + 512];                  // b_ih only
            float hold = hsm[tid * HROW + w];
            float r  = sigmoid_f(xr + ar[w]);
            float z  = sigmoid_f(xz + az[w]);
            float hn = bn + an[w];
            float nn = tanh_f(fmaf(r, hn, xn));
            float hnew = (1.f - z) * nn + z * hold;
            hsm[tid * HROW + w] = mk ? hnew : hold;      // freeze past seq end
        }
        __syncthreads();                                 // h visible next step
    }

    CP_WAITALL();                                        // drain tail copies

    // ---- final write: out[n, d*256 + i] = h * data_mask[n] -----------------
#pragma unroll
    for (int w = 0; w < WPB; w++) {
        const int n = wid_s[w];
        const float dm = data_mask[n] ? 1.f : 0.f;
        out[(size_t)n * 512 + d * 256 + tid] = hsm[tid * HROW + w] * dm;
    }
}

// ---------------------------------------------------------------------------
extern "C" void kernel_launch(void* const* d_in, const int* in_sizes, int n_in,
                              void* d_out, int out_size)
{
    const int*   chars      = (const int*)  d_in[0];
    const int*   chars_mask = (const int*)  d_in[1];
    const int*   data_mask  = (const int*)  d_in[2];
    const float* embed      = (const float*)d_in[3];
    const float* Wih_fw     = (const float*)d_in[4];
    const float* Whh_fw     = (const float*)d_in[5];
    const float* bih_fw     = (const float*)d_in[6];
    const float* bhh_fw     = (const float*)d_in[7];
    const float* Wih_bw     = (const float*)d_in[8];
    const float* Whh_bw     = (const float*)d_in[9];
    const float* bih_bw     = (const float*)d_in[10];
    const float* bhh_bw     = (const float*)d_in[11];
    float* out = (float*)d_out;

    static bool attr_done = false;
    if (!attr_done) {
        cudaFuncSetAttribute(gru_kernel,
                             cudaFuncAttributeMaxDynamicSharedMemorySize,
                             SMEM_BYTES);
        attr_done = true;
    }

    prep_tr_kernel<<<dim3(G3, 2), HH>>>(Whh_fw, Whh_bw, Wih_fw, Wih_bw);
    prep_p_kernel<<<dim3(NV, 2), 256>>>(embed, bih_fw, bhh_fw, bih_bw, bhh_bw);
    prep_sort_kernel<<<1, 1024>>>(chars_mask);
    gru_kernel<<<dim3(NTILES, 2), 256, SMEM_BYTES>>>(chars, chars_mask, data_mask,
                                                     bhh_fw, bhh_bw, out);
}

// round 11
// speedup vs baseline: 1.3547x; 1.3547x over previous
#include <cuda_runtime.h>
#include <cstdint>

// Problem constants
#define NB   32
#define NS   128
#define NW   4096      // NB*NS independent words
#define CC   32        // chars per word (time steps)
#define HH   256       // hidden
#define G3   768       // 3*H
#define EE   128       // embed dim
#define NV   262       // vocab
#define WPB  16        // words per block
#define HROW 20        // padded smem row for h (16 words + pad, 16B aligned)
#define NTILES (NW / WPB)           // 256

typedef unsigned long long u64;

// Precomputed x-projection table: P[d][v][j] = embed[v].W_ih[d][j] + b_ih[d][j]
// (+ b_hh[j] folded in for the r and z gates, j < 512)
__device__ float g_P[2][NV][G3];
// k-major transposed recurrent weights: g_Wt[d][k][j] = W_hh[d][j][k]
__device__ float g_Wt[2][HH][G3];
// k-major transposed input weights (for coalesced prep_p)
__device__ float g_WtI[2][EE][G3];
// k-quad packed recurrent weights (same bytes as g_Wt, 4 k per float4):
// g_W4[d][k4][g][j] = (w_k, w_k+1, w_k+2, w_k+3), k = 4*k4
__device__ float4 g_W4[2][HH / 4][3][256];
// length-sort structures
__device__ int g_len[NW];          // per-word char length
__device__ int g_perm[NW];         // word ids sorted by length DESCENDING
__device__ int g_bucket_pos[33];   // scatter cursors

// ---------------------------------------------------------------------------
// Packed fp32x2 helpers (Blackwell 2x-rate fp32; ptxas never auto-emits)
// ---------------------------------------------------------------------------
__device__ __forceinline__ void fma2(u64& d, u64 a, u64 b) {
    asm("fma.rn.f32x2 %0, %1, %2, %3;" : "=l"(d) : "l"(a), "l"(b), "l"(d));
}
__device__ __forceinline__ u64 dup2(float x) {
    u64 r;
    asm("mov.b64 %0, {%1, %1};" : "=l"(r) : "f"(x));
    return r;
}

// ---------------------------------------------------------------------------
// Prepack 0: transpose W_hh (768x256) and W_ih (768x128) to k-major.
// ---------------------------------------------------------------------------
__global__ void prep_tr_kernel(const float* __restrict__ Whh_fw,
                               const float* __restrict__ Whh_bw,
                               const float* __restrict__ Wih_fw,
                               const float* __restrict__ Wih_bw)
{
    int j = blockIdx.x;
    int d = blockIdx.y;
    int k = threadIdx.x;
    const float* Wh = d ? Whh_bw : Whh_fw;
    const float* Wi = d ? Wih_bw : Wih_fw;
    g_Wt[d][k][j] = Wh[(size_t)j * HH + k];
    if (k < EE) g_WtI[d][k][j] = Wi[(size_t)j * EE + k];
}

// ---------------------------------------------------------------------------
// Prepack 1: k-quad packed weight table (coalesced reads of g_Wt).
// ---------------------------------------------------------------------------
__global__ void prep_w4_kernel()
{
    int k4  = blockIdx.x;
    int d   = blockIdx.y;
    int tid = threadIdx.x;
#pragma unroll
    for (int g = 0; g < 3; g++) {
        float a = g_Wt[d][4 * k4 + 0][g * 256 + tid];
        float b = g_Wt[d][4 * k4 + 1][g * 256 + tid];
        float c = g_Wt[d][4 * k4 + 2][g * 256 + tid];
        float e = g_Wt[d][4 * k4 + 3][g * 256 + tid];
        g_W4[d][k4][g][tid] = make_float4(a, b, c, e);
    }
}

// ---------------------------------------------------------------------------
// Prepack 2: input-projection table, coalesced via g_WtI.  grid (NV, 2).
// ---------------------------------------------------------------------------
__global__ void prep_p_kernel(const float* __restrict__ embed,
                              const float* __restrict__ bih_fw,
                              const float* __restrict__ bhh_fw,
                              const float* __restrict__ bih_bw,
                              const float* __restrict__ bhh_bw)
{
    int v = blockIdx.x;
    int d = blockIdx.y;
    int tid = threadIdx.x;
    const float* bi = d ? bih_bw : bih_fw;
    const float* bh = d ? bhh_bw : bhh_fw;
    const float* ev = embed + (size_t)v * EE;
    float a0 = 0.f, a1 = 0.f, a2 = 0.f;
#pragma unroll 4
    for (int k = 0; k < EE; k++) {
        float e = __ldg(ev + k);                        // warp-broadcast
        const float* w = &g_WtI[d][k][0];
        a0 = fmaf(e, __ldg(w + tid),       a0);
        a1 = fmaf(e, __ldg(w + tid + 256), a1);
        a2 = fmaf(e, __ldg(w + tid + 512), a2);
    }
    g_P[d][v][tid]       = a0 + bi[tid]       + bh[tid];
    g_P[d][v][tid + 256] = a1 + bi[tid + 256] + bh[tid + 256];
    g_P[d][v][tid + 512] = a2 + bi[tid + 512];          // n-gate: b_hh NOT folded
}

// ---------------------------------------------------------------------------
// Prepack 3: counting sort of words by length, DESCENDING (contiguous-prefix
// mask -> len = row sum).  Output is permutation-invariant wrt scatter order.
// ---------------------------------------------------------------------------
__global__ void prep_sort_kernel(const int* __restrict__ chars_mask)
{
    __shared__ int hist[33];
    __shared__ int base[33];
    const int tid = threadIdx.x;
    if (tid < 33) hist[tid] = 0;
    __syncthreads();

    int mylen[NW / 1024];
#pragma unroll
    for (int q = 0; q < NW / 1024; q++) {
        const int n = tid + q * 1024;
        const int4* row = reinterpret_cast<const int4*>(chars_mask + n * CC);
        int len = 0;
#pragma unroll
        for (int c = 0; c < CC / 4; c++) {
            int4 m = __ldg(row + c);
            len += m.x + m.y + m.z + m.w;
        }
        mylen[q] = len;
        g_len[n] = len;
        atomicAdd(&hist[32 - len], 1);
    }
    __syncthreads();

    if (tid == 0) {
        int acc = 0;
        for (int b = 0; b < 33; b++) { base[b] = acc; acc += hist[b]; }
    }
    __syncthreads();
    if (tid < 33) g_bucket_pos[tid] = base[tid];
    __syncthreads();

#pragma unroll
    for (int q = 0; q < NW / 1024; q++) {
        const int n = tid + q * 1024;
        const int pos = atomicAdd(&g_bucket_pos[32 - mylen[q]], 1);
        g_perm[pos] = n;
    }
}

// ---------------------------------------------------------------------------
// Activations
// ---------------------------------------------------------------------------
__device__ __forceinline__ float sigmoid_f(float x) {
    return __fdividef(1.f, 1.f + __expf(-x));
}
__device__ __forceinline__ float tanh_f(float x) {
    x = fmaxf(-15.f, fminf(15.f, x));
    float e = __expf(-2.f * x);
    return __fdividef(1.f - e, 1.f + e);
}

// rank-1 update for one k: acc[word-pairs] += h[word-pairs] * w_gate
__device__ __forceinline__ void k_rank1(const float* __restrict__ hrow,
                                        float wr, float wz, float wn,
                                        u64* accr, u64* accz, u64* accn)
{
    const u64 wr2 = dup2(wr);
    const u64 wz2 = dup2(wz);
    const u64 wn2 = dup2(wn);
    const ulonglong2* __restrict__ hk = reinterpret_cast<const ulonglong2*>(hrow);
#pragma unroll
    for (int q = 0; q < WPB / 4; q++) {                  // 4 LDS.128 broadcast
        ulonglong2 a = hk[q];                            // words 4q..4q+3
        fma2(accr[2 * q],     a.x, wr2);
        fma2(accz[2 * q],     a.x, wz2);
        fma2(accn[2 * q],     a.x, wn2);
        fma2(accr[2 * q + 1], a.y, wr2);
        fma2(accz[2 * q + 1], a.y, wz2);
        fma2(accn[2 * q + 1], a.y, wn2);
    }
}

// ---------------------------------------------------------------------------
// Main recurrent kernel (R8 + k-quad weight LDG.128 + smem-cached epilogue).
// Tile = 16 length-sorted words (descending); runs only maxlen steps.
// Thread tid owns the (r,z,n) gate triple for hidden index i = tid; words
// packed in pairs into f32x2 lanes; h stored word-major per k in smem.
// Weights: 3 LDG.128 per 4k from the k-quad table (same bytes, fewer issue
// slots than 12 LDG.32), prefetched one kg-group ahead.  Epilogue reads
// chars/len from smem (preloaded once per tile) instead of scattered LDG.
// ---------------------------------------------------------------------------
__global__ void __launch_bounds__(256, 2) gru_kernel(
    const int*   __restrict__ chars,       // [NW, CC]
    const int*   __restrict__ data_mask,   // [NW]
    const float* __restrict__ bhh_fw,      // [G3]
    const float* __restrict__ bhh_bw,
    float*       __restrict__ out)         // [NW, 512]
{
    __shared__ float hsm[HH * HROW];       // h[k][word], 20KB
    __shared__ int   wid_s[WPB];           // real word ids of this tile
    __shared__ int   len_s[WPB];           // per-word lengths
    __shared__ int   chs[WPB][CC];         // per-tile char ids, 2KB

    const int tid  = threadIdx.x;
    const int d    = blockIdx.y;
    const int tile = blockIdx.x;

    const float4* __restrict__ W4 =
        reinterpret_cast<const float4*>(&g_W4[d][0][0][0]);  // [(k4*3+g)*256+j]
    const float bn = (d ? bhh_bw : bhh_fw)[tid + 512];       // n-gate bias

    if (tid < WPB) {
        const int n = g_perm[tile * WPB + tid];
        wid_s[tid] = n;
        len_s[tid] = g_len[n];
    }
    const int maxlen = __ldg(&g_len[__ldg(&g_perm[tile * WPB])]);  // first = longest

    // init h = 0
#pragma unroll
    for (int q = 0; q < HH * HROW / 256; q++)           // 20 stores/thread
        hsm[tid + q * 256] = 0.f;
    __syncthreads();

    // preload this tile's chars into smem (2 per thread)
#pragma unroll
    for (int q = 0; q < WPB * CC / 256; q++) {
        const int idx = tid + q * 256;
        const int w   = idx / CC;
        const int c   = idx % CC;
        chs[w][c] = __ldg(&chars[wid_s[w] * CC + c]);
    }
    __syncthreads();

    for (int step = 0; step < maxlen; step++) {
        const int t = d ? (maxlen - 1 - step) : step;

        // accumulators: 8 word-pairs x 3 gates, packed fp32x2
        u64 accr[WPB / 2], accz[WPB / 2], accn[WPB / 2];
#pragma unroll
        for (int p = 0; p < WPB / 2; p++) { accr[p] = 0ull; accz[p] = 0ull; accn[p] = 0ull; }

        // ---- gh = h @ W_hh^T; 4 k per iter, k-quad weights prefetched ------
        float4 c0 = __ldg(W4 + 0 * 256 + tid);           // r-gate, k 0..3
        float4 c1 = __ldg(W4 + 1 * 256 + tid);           // z-gate
        float4 c2 = __ldg(W4 + 2 * 256 + tid);           // n-gate
#pragma unroll 2
        for (int kg = 0; kg < HH / 4; kg++) {
            const int kn = (kg + 1 < HH / 4) ? (kg + 1) : kg;
            float4 p0 = __ldg(W4 + (kn * 3 + 0) * 256 + tid);
            float4 p1 = __ldg(W4 + (kn * 3 + 1) * 256 + tid);
            float4 p2 = __ldg(W4 + (kn * 3 + 2) * 256 + tid);

            k_rank1(&hsm[(4 * kg + 0) * HROW], c0.x, c1.x, c2.x, accr, accz, accn);
            k_rank1(&hsm[(4 * kg + 1) * HROW], c0.y, c1.y, c2.y, accr, accz, accn);
            k_rank1(&hsm[(4 * kg + 2) * HROW], c0.z, c1.z, c2.z, accr, accz, accn);
            k_rank1(&hsm[(4 * kg + 3) * HROW], c0.w, c1.w, c2.w, accr, accz, accn);

            c0 = p0; c1 = p1; c2 = p2;
        }

        // ---- gates (thread-local), update h --------------------------------
        __syncthreads();                                 // all h reads done
        const float* ar = reinterpret_cast<const float*>(accr);
        const float* az = reinterpret_cast<const float*>(accz);
        const float* an = reinterpret_cast<const float*>(accn);
#pragma unroll
        for (int w = 0; w < WPB; w++) {
            const int ch = chs[w][t];                    // LDS broadcast
            const int mk = (t < len_s[w]);               // mask from length
            const float* __restrict__ Prow = &g_P[d][ch][0];
            float xr = Prow[tid];                        // b_ih + b_hh folded
            float xz = Prow[tid + 256];
            float xn = Prow[tid + 512];                  // b_ih only
            float hold = hsm[tid * HROW + w];
            float r  = sigmoid_f(xr + ar[w]);
            float z  = sigmoid_f(xz + az[w]);
            float hn = bn + an[w];
            float nn = tanh_f(fmaf(r, hn, xn));
            float hnew = (1.f - z) * nn + z * hold;
            hsm[tid * HROW + w] = mk ? hnew : hold;      // freeze past seq end
        }
        __syncthreads();                                 // h visible next step
    }

    // ---- final write: out[n, d*256 + i] = h * data_mask[n] -----------------
#pragma unroll
    for (int w = 0; w < WPB; w++) {
        const int n = wid_s[w];
        const float dm = data_mask[n] ? 1.f : 0.f;
        out[(size_t)n * 512 + d * 256 + tid] = hsm[tid * HROW + w] * dm;
    }
}

// ---------------------------------------------------------------------------
extern "C" void kernel_launch(void* const* d_in, const int* in_sizes, int n_in,
                              void* d_out, int out_size)
{
    const int*   chars      = (const int*)  d_in[0];
    const int*   chars_mask = (const int*)  d_in[1];
    const int*   data_mask  = (const int*)  d_in[2];
    const float* embed      = (const float*)d_in[3];
    const float* Wih_fw     = (const float*)d_in[4];
    const float* Whh_fw     = (const float*)d_in[5];
    const float* bih_fw     = (const float*)d_in[6];
    const float* bhh_fw     = (const float*)d_in[7];
    const float* Wih_bw     = (const float*)d_in[8];
    const float* Whh_bw     = (const float*)d_in[9];
    const float* bih_bw     = (const float*)d_in[10];
    const float* bhh_bw     = (const float*)d_in[11];
    float* out = (float*)d_out;

    prep_tr_kernel<<<dim3(G3, 2), HH>>>(Whh_fw, Whh_bw, Wih_fw, Wih_bw);
    prep_w4_kernel<<<dim3(HH / 4, 2), 256>>>();
    prep_p_kernel<<<dim3(NV, 2), 256>>>(embed, bih_fw, bhh_fw, bih_bw, bhh_bw);
    prep_sort_kernel<<<1, 1024>>>(chars_mask);
    gru_kernel<<<dim3(NTILES, 2), 256>>>(chars, data_mask, bhh_fw, bhh_bw, out);
}

// round 12
// speedup vs baseline: 1.4392x; 1.0624x over previous
#include <cuda_runtime.h>
#include <cstdint>

// Problem constants
#define NB   32
#define NS   128
#define NW   4096      // NB*NS independent words
#define CC   32        // chars per word (time steps)
#define HH   256       // hidden
#define G3   768       // 3*H
#define EE   128       // embed dim
#define NV   262       // vocab
#define WPB  16        // words per block
#define HROW 20        // padded smem row for h (16 words + pad, 16B aligned)
#define NTILES (NW / WPB)           // 256

typedef unsigned long long u64;

// Precomputed x-projection table: P[d][v][j] = embed[v].W_ih[d][j] + b_ih[d][j]
// (+ b_hh[j] folded in for the r and z gates, j < 512)
__device__ float g_P[2][NV][G3];
// k-major transposed recurrent weights: g_Wt[d][k][j] = W_hh[d][j][k]
__device__ float g_Wt[2][HH][G3];
// k-major transposed input weights (for coalesced prep_p)
__device__ float g_WtI[2][EE][G3];
// k-quad packed recurrent weights (same bytes as g_Wt, 4 k per float4):
// g_W4[d][k4][g][j] = (w_k, w_k+1, w_k+2, w_k+3), k = 4*k4
__device__ float4 g_W4[2][HH / 4][3][256];
// length-sort structures
__device__ int g_len[NW];          // per-word char length
__device__ int g_perm[NW];         // word ids sorted by length DESCENDING
__device__ int g_bucket_pos[33];   // scatter cursors

// ---------------------------------------------------------------------------
// Packed fp32x2 helpers (Blackwell 2x-rate fp32; ptxas never auto-emits)
// ---------------------------------------------------------------------------
__device__ __forceinline__ void fma2(u64& d, u64 a, u64 b) {
    asm("fma.rn.f32x2 %0, %1, %2, %3;" : "=l"(d) : "l"(a), "l"(b), "l"(d));
}
__device__ __forceinline__ u64 dup2(float x) {
    u64 r;
    asm("mov.b64 %0, {%1, %1};" : "=l"(r) : "f"(x));
    return r;
}

// ---------------------------------------------------------------------------
// Prepack 0: transpose W_hh (768x256) and W_ih (768x128) to k-major.
// ---------------------------------------------------------------------------
__global__ void prep_tr_kernel(const float* __restrict__ Whh_fw,
                               const float* __restrict__ Whh_bw,
                               const float* __restrict__ Wih_fw,
                               const float* __restrict__ Wih_bw)
{
    int j = blockIdx.x;
    int d = blockIdx.y;
    int k = threadIdx.x;
    const float* Wh = d ? Whh_bw : Whh_fw;
    const float* Wi = d ? Wih_bw : Wih_fw;
    g_Wt[d][k][j] = Wh[(size_t)j * HH + k];
    if (k < EE) g_WtI[d][k][j] = Wi[(size_t)j * EE + k];
}

// ---------------------------------------------------------------------------
// Prepack 1: k-quad packed weight table (coalesced reads of g_Wt).
// ---------------------------------------------------------------------------
__global__ void prep_w4_kernel()
{
    int k4  = blockIdx.x;
    int d   = blockIdx.y;
    int tid = threadIdx.x;
#pragma unroll
    for (int g = 0; g < 3; g++) {
        float a = g_Wt[d][4 * k4 + 0][g * 256 + tid];
        float b = g_Wt[d][4 * k4 + 1][g * 256 + tid];
        float c = g_Wt[d][4 * k4 + 2][g * 256 + tid];
        float e = g_Wt[d][4 * k4 + 3][g * 256 + tid];
        g_W4[d][k4][g][tid] = make_float4(a, b, c, e);
    }
}

// ---------------------------------------------------------------------------
// Prepack 2: input-projection table, coalesced via g_WtI.  grid (NV, 2).
// ---------------------------------------------------------------------------
__global__ void prep_p_kernel(const float* __restrict__ embed,
                              const float* __restrict__ bih_fw,
                              const float* __restrict__ bhh_fw,
                              const float* __restrict__ bih_bw,
                              const float* __restrict__ bhh_bw)
{
    int v = blockIdx.x;
    int d = blockIdx.y;
    int tid = threadIdx.x;
    const float* bi = d ? bih_bw : bih_fw;
    const float* bh = d ? bhh_bw : bhh_fw;
    const float* ev = embed + (size_t)v * EE;
    float a0 = 0.f, a1 = 0.f, a2 = 0.f;
#pragma unroll 4
    for (int k = 0; k < EE; k++) {
        float e = __ldg(ev + k);                        // warp-broadcast
        const float* w = &g_WtI[d][k][0];
        a0 = fmaf(e, __ldg(w + tid),       a0);
        a1 = fmaf(e, __ldg(w + tid + 256), a1);
        a2 = fmaf(e, __ldg(w + tid + 512), a2);
    }
    g_P[d][v][tid]       = a0 + bi[tid]       + bh[tid];
    g_P[d][v][tid + 256] = a1 + bi[tid + 256] + bh[tid + 256];
    g_P[d][v][tid + 512] = a2 + bi[tid + 512];          // n-gate: b_hh NOT folded
}

// ---------------------------------------------------------------------------
// Prepack 3a: per-word lengths, grid-parallel (contiguous-prefix mask).
// ---------------------------------------------------------------------------
__global__ void prep_len_kernel(const int* __restrict__ chars_mask)
{
    const int n = blockIdx.x * blockDim.x + threadIdx.x;
    const int4* row = reinterpret_cast<const int4*>(chars_mask + n * CC);
    int len = 0;
#pragma unroll
    for (int c = 0; c < CC / 4; c++) {
        int4 m = __ldg(row + c);
        len += m.x + m.y + m.z + m.w;
    }
    g_len[n] = len;
}

// ---------------------------------------------------------------------------
// Prepack 3b: counting sort by length DESCENDING (reads only g_len).
// Single block; output permutation-invariant wrt scatter order.
// ---------------------------------------------------------------------------
__global__ void prep_sort_kernel()
{
    __shared__ int hist[33];
    __shared__ int base[33];
    const int tid = threadIdx.x;
    if (tid < 33) hist[tid] = 0;
    __syncthreads();

    int mylen[NW / 1024];
#pragma unroll
    for (int q = 0; q < NW / 1024; q++) {
        mylen[q] = g_len[tid + q * 1024];
        atomicAdd(&hist[32 - mylen[q]], 1);
    }
    __syncthreads();

    if (tid == 0) {
        int acc = 0;
        for (int b = 0; b < 33; b++) { base[b] = acc; acc += hist[b]; }
    }
    __syncthreads();
    if (tid < 33) g_bucket_pos[tid] = base[tid];
    __syncthreads();

#pragma unroll
    for (int q = 0; q < NW / 1024; q++) {
        const int pos = atomicAdd(&g_bucket_pos[32 - mylen[q]], 1);
        g_perm[pos] = tid + q * 1024;
    }
}

// ---------------------------------------------------------------------------
// Activations
// ---------------------------------------------------------------------------
__device__ __forceinline__ float sigmoid_f(float x) {
    return __fdividef(1.f, 1.f + __expf(-x));
}
__device__ __forceinline__ float tanh_f(float x) {
    x = fmaxf(-15.f, fminf(15.f, x));
    float e = __expf(-2.f * x);
    return __fdividef(1.f - e, 1.f + e);
}

// rank-1 update for one k: acc[word-pairs] += h[word-pairs] * w_gate
__device__ __forceinline__ void k_rank1(const float* __restrict__ hrow,
                                        float wr, float wz, float wn,
                                        u64* accr, u64* accz, u64* accn)
{
    const u64 wr2 = dup2(wr);
    const u64 wz2 = dup2(wz);
    const u64 wn2 = dup2(wn);
    const ulonglong2* __restrict__ hk = reinterpret_cast<const ulonglong2*>(hrow);
#pragma unroll
    for (int q = 0; q < WPB / 4; q++) {                  // 4 LDS.128 broadcast
        ulonglong2 a = hk[q];                            // words 4q..4q+3
        fma2(accr[2 * q],     a.x, wr2);
        fma2(accz[2 * q],     a.x, wz2);
        fma2(accn[2 * q],     a.x, wn2);
        fma2(accr[2 * q + 1], a.y, wr2);
        fma2(accz[2 * q + 1], a.y, wz2);
        fma2(accn[2 * q + 1], a.y, wn2);
    }
}

// ---------------------------------------------------------------------------
// Main recurrent kernel (R10 + double-buffered h + batched epilogue loads).
// Double-buffered h: GEMV reads buf[s&1], epilogue writes buf[(s+1)&1] ->
// only ONE __syncthreads per step, and warps drift freely between their own
// GEMV and epilogue (FFMA2 / MUFU / LDG overlap across warps).
// Epilogue processes words in groups of 4 with all 12 P-row LDGs issued
// up-front (MLP 12 vs ~3) to compress exposed L2 latency.
// ---------------------------------------------------------------------------
__global__ void __launch_bounds__(256, 2) gru_kernel(
    const int*   __restrict__ chars,       // [NW, CC]
    const int*   __restrict__ data_mask,   // [NW]
    const float* __restrict__ bhh_fw,      // [G3]
    const float* __restrict__ bhh_bw,
    float*       __restrict__ out)         // [NW, 512]
{
    __shared__ float hsm[2][HH * HROW];    // double-buffered h, 40KB
    __shared__ int   wid_s[WPB];           // real word ids of this tile
    __shared__ int   len_s[WPB];           // per-word lengths
    __shared__ int   chs[WPB][CC];         // per-tile char ids, 2KB

    const int tid  = threadIdx.x;
    const int d    = blockIdx.y;
    const int tile = blockIdx.x;

    const float4* __restrict__ W4 =
        reinterpret_cast<const float4*>(&g_W4[d][0][0][0]);  // [(k4*3+g)*256+j]
    const float bn = (d ? bhh_bw : bhh_fw)[tid + 512];       // n-gate bias

    if (tid < WPB) {
        const int n = g_perm[tile * WPB + tid];
        wid_s[tid] = n;
        len_s[tid] = g_len[n];
    }
    const int maxlen = __ldg(&g_len[__ldg(&g_perm[tile * WPB])]);  // first = longest

    // init h buffer 0 = 0
#pragma unroll
    for (int q = 0; q < HH * HROW / 256; q++)           // 20 stores/thread
        hsm[0][tid + q * 256] = 0.f;
    __syncthreads();

    // preload this tile's chars into smem (2 per thread)
#pragma unroll
    for (int q = 0; q < WPB * CC / 256; q++) {
        const int idx = tid + q * 256;
        const int w   = idx / CC;
        const int c   = idx % CC;
        chs[w][c] = __ldg(&chars[wid_s[w] * CC + c]);
    }
    __syncthreads();

    for (int step = 0; step < maxlen; step++) {
        const int t = d ? (maxlen - 1 - step) : step;
        const float* __restrict__ rb = hsm[step & 1];        // read buffer
        float*       __restrict__ wbv = hsm[(step + 1) & 1]; // write buffer

        // accumulators: 8 word-pairs x 3 gates, packed fp32x2
        u64 accr[WPB / 2], accz[WPB / 2], accn[WPB / 2];
#pragma unroll
        for (int p = 0; p < WPB / 2; p++) { accr[p] = 0ull; accz[p] = 0ull; accn[p] = 0ull; }

        // ---- gh = h @ W_hh^T; 4 k per iter, k-quad weights prefetched ------
        float4 c0 = __ldg(W4 + 0 * 256 + tid);           // r-gate, k 0..3
        float4 c1 = __ldg(W4 + 1 * 256 + tid);           // z-gate
        float4 c2 = __ldg(W4 + 2 * 256 + tid);           // n-gate
#pragma unroll 2
        for (int kg = 0; kg < HH / 4; kg++) {
            const int kn = (kg + 1 < HH / 4) ? (kg + 1) : kg;
            float4 p0 = __ldg(W4 + (kn * 3 + 0) * 256 + tid);
            float4 p1 = __ldg(W4 + (kn * 3 + 1) * 256 + tid);
            float4 p2 = __ldg(W4 + (kn * 3 + 2) * 256 + tid);

            k_rank1(&rb[(4 * kg + 0) * HROW], c0.x, c1.x, c2.x, accr, accz, accn);
            k_rank1(&rb[(4 * kg + 1) * HROW], c0.y, c1.y, c2.y, accr, accz, accn);
            k_rank1(&rb[(4 * kg + 2) * HROW], c0.z, c1.z, c2.z, accr, accz, accn);
            k_rank1(&rb[(4 * kg + 3) * HROW], c0.w, c1.w, c2.w, accr, accz, accn);

            c0 = p0; c1 = p1; c2 = p2;
        }

        // ---- gates, update h into the OTHER buffer (no barrier needed) -----
        const float* ar = reinterpret_cast<const float*>(accr);
        const float* az = reinterpret_cast<const float*>(accz);
        const float* an = reinterpret_cast<const float*>(accn);
#pragma unroll
        for (int g4 = 0; g4 < WPB / 4; g4++) {
            float xr[4], xz[4], xn[4];
#pragma unroll
            for (int j = 0; j < 4; j++) {                // batch 12 LDGs (MLP)
                const int w = 4 * g4 + j;
                const float* __restrict__ Prow = &g_P[d][chs[w][t]][0];
                xr[j] = __ldg(Prow + tid);               // b_ih + b_hh folded
                xz[j] = __ldg(Prow + tid + 256);
                xn[j] = __ldg(Prow + tid + 512);         // b_ih only
            }
#pragma unroll
            for (int j = 0; j < 4; j++) {
                const int w  = 4 * g4 + j;
                const int mk = (t < len_s[w]);
                float hold = rb[tid * HROW + w];
                float r  = sigmoid_f(xr[j] + ar[w]);
                float z  = sigmoid_f(xz[j] + az[w]);
                float hn = bn + an[w];
                float nn = tanh_f(fmaf(r, hn, xn[j]));
                float hnew = (1.f - z) * nn + z * hold;
                wbv[tid * HROW + w] = mk ? hnew : hold;  // freeze past seq end
            }
        }
        __syncthreads();                                 // wbv visible; rb free
    }

    // ---- final write: out[n, d*256 + i] = h * data_mask[n] -----------------
    const float* hb = hsm[maxlen & 1];
#pragma unroll
    for (int w = 0; w < WPB; w++) {
        const int n = wid_s[w];
        const float dm = data_mask[n] ? 1.f : 0.f;
        out[(size_t)n * 512 + d * 256 + tid] = hb[tid * HROW + w] * dm;
    }
}

// ---------------------------------------------------------------------------
extern "C" void kernel_launch(void* const* d_in, const int* in_sizes, int n_in,
                              void* d_out, int out_size)
{
    const int*   chars      = (const int*)  d_in[0];
    const int*   chars_mask = (const int*)  d_in[1];
    const int*   data_mask  = (const int*)  d_in[2];
    const float* embed      = (const float*)d_in[3];
    const float* Wih_fw     = (const float*)d_in[4];
    const float* Whh_fw     = (const float*)d_in[5];
    const float* bih_fw     = (const float*)d_in[6];
    const float* bhh_fw     = (const float*)d_in[7];
    const float* Wih_bw     = (const float*)d_in[8];
    const float* Whh_bw     = (const float*)d_in[9];
    const float* bih_bw     = (const float*)d_in[10];
    const float* bhh_bw     = (const float*)d_in[11];
    float* out = (float*)d_out;

    prep_tr_kernel<<<dim3(G3, 2), HH>>>(Whh_fw, Whh_bw, Wih_fw, Wih_bw);
    prep_w4_kernel<<<dim3(HH / 4, 2), 256>>>();
    prep_p_kernel<<<dim3(NV, 2), 256>>>(embed, bih_fw, bhh_fw, bih_bw, bhh_bw);
    prep_len_kernel<<<NW / 256, 256>>>(chars_mask);
    prep_sort_kernel<<<1, 1024>>>();
    gru_kernel<<<dim3(NTILES, 2), 256>>>(chars, data_mask, bhh_fw, bhh_bw, out);
}

// round 13
// speedup vs baseline: 1.4743x; 1.0244x over previous
#include <cuda_runtime.h>
#include <cstdint>

// Problem constants
#define NB   32
#define NS   128
#define NW   4096      // NB*NS independent words
#define CC   32        // chars per word (time steps)
#define HH   256       // hidden
#define G3   768       // 3*H
#define EE   128       // embed dim
#define NV   262       // vocab
#define WPB  16        // words per block
#define HROW 20        // padded smem row for h (16 words + pad, 16B aligned)
#define NTILES (NW / WPB)           // 256

typedef unsigned long long u64;

// Precomputed x-projection table: P[d][v][j] = embed[v].W_ih[d][j] + b_ih[d][j]
// (+ b_hh[j] folded in for the r and z gates, j < 512)
__device__ float g_P[2][NV][G3];
// k-major transposed input weights (for coalesced prep_p)
__device__ float g_WtI[2][EE][G3];
// k-quad packed recurrent weights: g_W4[d][k4][g][j] = W_hh[g*256+j][4k4..4k4+3]
// one PAD slot at k4 = HH/4 so the gru prefetch needs no end-clamp
__device__ float4 g_W4[2][HH / 4 + 1][3][256];
// length-sort structures
__device__ int g_len[NW];          // per-word char length
__device__ int g_perm[NW];         // word ids sorted by length DESCENDING
__device__ int g_bucket_pos[33];   // scatter cursors

// ---------------------------------------------------------------------------
// Packed fp32x2 helpers (Blackwell 2x-rate fp32; ptxas never auto-emits)
// ---------------------------------------------------------------------------
__device__ __forceinline__ void fma2(u64& d, u64 a, u64 b) {
    asm("fma.rn.f32x2 %0, %1, %2, %3;" : "=l"(d) : "l"(a), "l"(b), "l"(d));
}
__device__ __forceinline__ u64 dup2(float x) {
    u64 r;
    asm("mov.b64 %0, {%1, %1};" : "=l"(r) : "f"(x));
    return r;
}

// ---------------------------------------------------------------------------
// Prepack 0: transpose W_ih (768x128) to k-major (for coalesced prep_p).
// grid (G3, 2), EE threads.
// ---------------------------------------------------------------------------
__global__ void prep_tr_kernel(const float* __restrict__ Wih_fw,
                               const float* __restrict__ Wih_bw)
{
    int j = blockIdx.x;
    int d = blockIdx.y;
    int k = threadIdx.x;
    const float* Wi = d ? Wih_bw : Wih_fw;
    g_WtI[d][k][j] = Wi[(size_t)j * EE + k];
}

// ---------------------------------------------------------------------------
// Prepack 1: k-quad packed weight table straight from W_hh (row-major).
// grid (G3, 2), 64 threads (one per k4); reads coalesced float4 per row.
// ---------------------------------------------------------------------------
__global__ void prep_w4_kernel(const float* __restrict__ Whh_fw,
                               const float* __restrict__ Whh_bw)
{
    const int row = blockIdx.x;          // j-row of W_hh: gate g = row/256
    const int d   = blockIdx.y;
    const int k4  = threadIdx.x;         // 0..63
    const float* W = d ? Whh_bw : Whh_fw;
    float4 v = reinterpret_cast<const float4*>(W + (size_t)row * HH)[k4];
    g_W4[d][k4][row >> 8][row & 255] = v;
    if (k4 == 0)                          // zero the pad slot once per row
        g_W4[d][HH / 4][row >> 8][row & 255] = make_float4(0.f, 0.f, 0.f, 0.f);
}

// ---------------------------------------------------------------------------
// Prepack 2: input-projection table, coalesced via g_WtI.  grid (NV, 2).
// ---------------------------------------------------------------------------
__global__ void prep_p_kernel(const float* __restrict__ embed,
                              const float* __restrict__ bih_fw,
                              const float* __restrict__ bhh_fw,
                              const float* __restrict__ bih_bw,
                              const float* __restrict__ bhh_bw)
{
    int v = blockIdx.x;
    int d = blockIdx.y;
    int tid = threadIdx.x;
    const float* bi = d ? bih_bw : bih_fw;
    const float* bh = d ? bhh_bw : bhh_fw;
    const float* ev = embed + (size_t)v * EE;
    float a0 = 0.f, a1 = 0.f, a2 = 0.f;
#pragma unroll 4
    for (int k = 0; k < EE; k++) {
        float e = __ldg(ev + k);                        // warp-broadcast
        const float* w = &g_WtI[d][k][0];
        a0 = fmaf(e, __ldg(w + tid),       a0);
        a1 = fmaf(e, __ldg(w + tid + 256), a1);
        a2 = fmaf(e, __ldg(w + tid + 512), a2);
    }
    g_P[d][v][tid]       = a0 + bi[tid]       + bh[tid];
    g_P[d][v][tid + 256] = a1 + bi[tid + 256] + bh[tid + 256];
    g_P[d][v][tid + 512] = a2 + bi[tid + 512];          // n-gate: b_hh NOT folded
}

// ---------------------------------------------------------------------------
// Prepack 3a: per-word lengths, grid-parallel (contiguous-prefix mask).
// ---------------------------------------------------------------------------
__global__ void prep_len_kernel(const int* __restrict__ chars_mask)
{
    const int n = blockIdx.x * blockDim.x + threadIdx.x;
    const int4* row = reinterpret_cast<const int4*>(chars_mask + n * CC);
    int len = 0;
#pragma unroll
    for (int c = 0; c < CC / 4; c++) {
        int4 m = __ldg(row + c);
        len += m.x + m.y + m.z + m.w;
    }
    g_len[n] = len;
}

// ---------------------------------------------------------------------------
// Prepack 3b: counting sort by length DESCENDING (reads only g_len).
// Single block; output permutation-invariant wrt scatter order.
// ---------------------------------------------------------------------------
__global__ void prep_sort_kernel()
{
    __shared__ int hist[33];
    __shared__ int base[33];
    const int tid = threadIdx.x;
    if (tid < 33) hist[tid] = 0;
    __syncthreads();

    int mylen[NW / 1024];
#pragma unroll
    for (int q = 0; q < NW / 1024; q++) {
        mylen[q] = g_len[tid + q * 1024];
        atomicAdd(&hist[32 - mylen[q]], 1);
    }
    __syncthreads();

    if (tid == 0) {
        int acc = 0;
        for (int b = 0; b < 33; b++) { base[b] = acc; acc += hist[b]; }
    }
    __syncthreads();
    if (tid < 33) g_bucket_pos[tid] = base[tid];
    __syncthreads();

#pragma unroll
    for (int q = 0; q < NW / 1024; q++) {
        const int pos = atomicAdd(&g_bucket_pos[32 - mylen[q]], 1);
        g_perm[pos] = tid + q * 1024;
    }
}

// ---------------------------------------------------------------------------
// Activations
// ---------------------------------------------------------------------------
__device__ __forceinline__ float sigmoid_f(float x) {
    return __fdividef(1.f, 1.f + __expf(-x));
}
__device__ __forceinline__ float tanh_f(float x) {
    x = fmaxf(-15.f, fminf(15.f, x));
    float e = __expf(-2.f * x);
    return __fdividef(1.f - e, 1.f + e);
}

// rank-1 update for one k: acc[word-pairs] += h[word-pairs] * w_gate
__device__ __forceinline__ void k_rank1(const float* __restrict__ hrow,
                                        float wr, float wz, float wn,
                                        u64* accr, u64* accz, u64* accn)
{
    const u64 wr2 = dup2(wr);
    const u64 wz2 = dup2(wz);
    const u64 wn2 = dup2(wn);
    const ulonglong2* __restrict__ hk = reinterpret_cast<const ulonglong2*>(hrow);
#pragma unroll
    for (int q = 0; q < WPB / 4; q++) {                  // 4 LDS.128 broadcast
        ulonglong2 a = hk[q];                            // words 4q..4q+3
        fma2(accr[2 * q],     a.x, wr2);
        fma2(accz[2 * q],     a.x, wz2);
        fma2(accn[2 * q],     a.x, wn2);
        fma2(accr[2 * q + 1], a.y, wr2);
        fma2(accz[2 * q + 1], a.y, wz2);
        fma2(accn[2 * q + 1], a.y, wn2);
    }
}

// ---------------------------------------------------------------------------
// Main recurrent kernel (R11 + padded-prefetch + unroll4 + interleaved grid).
// grid.x = 2*NTILES linear: tile = bx>>1, d = bx&1 -> launch order strictly
// descending tile length in BOTH directions (better tail than dir-major).
// Double-buffered h: one __syncthreads per step, warps drift between their
// GEMV and epilogue.  Weights: 3 LDG.128 per 4k from the padded k-quad
// table, prefetched one kg-group ahead with no end-clamp.
// ---------------------------------------------------------------------------
__global__ void __launch_bounds__(256, 2) gru_kernel(
    const int*   __restrict__ chars,       // [NW, CC]
    const int*   __restrict__ data_mask,   // [NW]
    const float* __restrict__ bhh_fw,      // [G3]
    const float* __restrict__ bhh_bw,
    float*       __restrict__ out)         // [NW, 512]
{
    __shared__ float hsm[2][HH * HROW];    // double-buffered h, 40KB
    __shared__ int   wid_s[WPB];           // real word ids of this tile
    __shared__ int   len_s[WPB];           // per-word lengths
    __shared__ int   chs[WPB][CC];         // per-tile char ids, 2KB

    const int tid  = threadIdx.x;
    const int tile = blockIdx.x >> 1;
    const int d    = blockIdx.x & 1;

    const float4* __restrict__ W4 =
        reinterpret_cast<const float4*>(&g_W4[d][0][0][0]);  // [(k4*3+g)*256+j]
    const float bn = (d ? bhh_bw : bhh_fw)[tid + 512];       // n-gate bias

    if (tid < WPB) {
        const int n = g_perm[tile * WPB + tid];
        wid_s[tid] = n;
        len_s[tid] = g_len[n];
    }
    const int maxlen = __ldg(&g_len[__ldg(&g_perm[tile * WPB])]);  // first = longest

    // init h buffer 0 = 0
#pragma unroll
    for (int q = 0; q < HH * HROW / 256; q++)           // 20 stores/thread
        hsm[0][tid + q * 256] = 0.f;
    __syncthreads();

    // preload this tile's chars into smem (2 per thread)
#pragma unroll
    for (int q = 0; q < WPB * CC / 256; q++) {
        const int idx = tid + q * 256;
        const int w   = idx / CC;
        const int c   = idx % CC;
        chs[w][c] = __ldg(&chars[wid_s[w] * CC + c]);
    }
    __syncthreads();

    for (int step = 0; step < maxlen; step++) {
        const int t = d ? (maxlen - 1 - step) : step;
        const float* __restrict__ rb = hsm[step & 1];        // read buffer
        float*       __restrict__ wbv = hsm[(step + 1) & 1]; // write buffer

        // accumulators: 8 word-pairs x 3 gates, packed fp32x2
        u64 accr[WPB / 2], accz[WPB / 2], accn[WPB / 2];
#pragma unroll
        for (int p = 0; p < WPB / 2; p++) { accr[p] = 0ull; accz[p] = 0ull; accn[p] = 0ull; }

        // ---- gh = h @ W_hh^T; 4 k per iter, padded prefetch (no clamp) -----
        float4 c0 = __ldg(W4 + 0 * 256 + tid);           // r-gate, k 0..3
        float4 c1 = __ldg(W4 + 1 * 256 + tid);           // z-gate
        float4 c2 = __ldg(W4 + 2 * 256 + tid);           // n-gate
#pragma unroll 4
        for (int kg = 0; kg < HH / 4; kg++) {
            const int kn = kg + 1;                       // pad slot makes this safe
            float4 p0 = __ldg(W4 + (kn * 3 + 0) * 256 + tid);
            float4 p1 = __ldg(W4 + (kn * 3 + 1) * 256 + tid);
            float4 p2 = __ldg(W4 + (kn * 3 + 2) * 256 + tid);

            k_rank1(&rb[(4 * kg + 0) * HROW], c0.x, c1.x, c2.x, accr, accz, accn);
            k_rank1(&rb[(4 * kg + 1) * HROW], c0.y, c1.y, c2.y, accr, accz, accn);
            k_rank1(&rb[(4 * kg + 2) * HROW], c0.z, c1.z, c2.z, accr, accz, accn);
            k_rank1(&rb[(4 * kg + 3) * HROW], c0.w, c1.w, c2.w, accr, accz, accn);

            c0 = p0; c1 = p1; c2 = p2;
        }

        // ---- gates, update h into the OTHER buffer (no barrier needed) -----
        const float* ar = reinterpret_cast<const float*>(accr);
        const float* az = reinterpret_cast<const float*>(accz);
        const float* an = reinterpret_cast<const float*>(accn);
#pragma unroll
        for (int g4 = 0; g4 < WPB / 4; g4++) {
            float xr[4], xz[4], xn[4], hold[4];
#pragma unroll
            for (int j = 0; j < 4; j++) {                // batch loads (MLP)
                const int w = 4 * g4 + j;
                const float* __restrict__ Prow = &g_P[d][chs[w][t]][0];
                xr[j] = __ldg(Prow + tid);               // b_ih + b_hh folded
                xz[j] = __ldg(Prow + tid + 256);
                xn[j] = __ldg(Prow + tid + 512);         // b_ih only
                hold[j] = rb[tid * HROW + w];
            }
#pragma unroll
            for (int j = 0; j < 4; j++) {
                const int w  = 4 * g4 + j;
                const int mk = (t < len_s[w]);
                float r  = sigmoid_f(xr[j] + ar[w]);
                float z  = sigmoid_f(xz[j] + az[w]);
                float hn = bn + an[w];
                float nn = tanh_f(fmaf(r, hn, xn[j]));
                float hnew = (1.f - z) * nn + z * hold[j];
                wbv[tid * HROW + w] = mk ? hnew : hold[j];  // freeze past end
            }
        }
        __syncthreads();                                 // wbv visible; rb free
    }

    // ---- final write: out[n, d*256 + i] = h * data_mask[n] -----------------
    const float* hb = hsm[maxlen & 1];
#pragma unroll
    for (int w = 0; w < WPB; w++) {
        const int n = wid_s[w];
        const float dm = data_mask[n] ? 1.f : 0.f;
        out[(size_t)n * 512 + d * 256 + tid] = hb[tid * HROW + w] * dm;
    }
}

// ---------------------------------------------------------------------------
extern "C" void kernel_launch(void* const* d_in, const int* in_sizes, int n_in,
                              void* d_out, int out_size)
{
    const int*   chars      = (const int*)  d_in[0];
    const int*   chars_mask = (const int*)  d_in[1];
    const int*   data_mask  = (const int*)  d_in[2];
    const float* embed      = (const float*)d_in[3];
    const float* Wih_fw     = (const float*)d_in[4];
    const float* Whh_fw     = (const float*)d_in[5];
    const float* bih_fw     = (const float*)d_in[6];
    const float* bhh_fw     = (const float*)d_in[7];
    const float* Wih_bw     = (const float*)d_in[8];
    const float* Whh_bw     = (const float*)d_in[9];
    const float* bih_bw     = (const float*)d_in[10];
    const float* bhh_bw     = (const float*)d_in[11];
    float* out = (float*)d_out;

    prep_tr_kernel<<<dim3(G3, 2), EE>>>(Wih_fw, Wih_bw);
    prep_w4_kernel<<<dim3(G3, 2), HH / 4>>>(Whh_fw, Whh_bw);
    prep_p_kernel<<<dim3(NV, 2), 256>>>(embed, bih_fw, bhh_fw, bih_bw, bhh_bw);
    prep_len_kernel<<<NW / 256, 256>>>(chars_mask);
    prep_sort_kernel<<<1, 1024>>>();
    gru_kernel<<<dim3(2 * NTILES, 1), 256>>>(chars, data_mask, bhh_fw, bhh_bw, out);
}